// round 1
// baseline (speedup 1.0000x reference)
#include <cuda_runtime.h>
#include <math.h>

// Problem constants (shapes fixed by the dataset)
#define B_    4
#define S0    12
#define T_    24          // template side (2*s0)
#define S_    576         // T_*T_
#define DIM   256
#define NP    128         // nPnt
#define HID   512         // 4*nPnt
#define S2    48          // new2 = 2*new_size
#define H_    120
#define W_    160

// ---------------- scratch (device globals; no allocation allowed) -------------
__device__ float g_t   [B_ * S_ * DIM];      // template tokens [4,576,256]
__device__ float g_A0  [B_ * S_ * NP];       // t @ P^T / 16
__device__ float g_H   [B_ * S_ * HID];      // MLP hidden (reused nr/na)
__device__ float g_adj [B_ * S_ * NP];       // node_adj after nr MLP
__device__ float g_attn[B_ * S_ * NP];       // na MLP out, then softmax in-place
__device__ float g_tokn[(long)B_ * S2 * NP * DIM];  // token_n [4,48,128,256]
__device__ float g_fus [B_ * NP * DIM];      // token_fused [4,128,256]
__device__ float g_U   [B_ * S_ * DIM];      // unique output rows

__device__ __forceinline__ float gelu_exact(float x) {
    return 0.5f * x * (1.0f + erff(x * 0.70710678118654752440f));
}

// ---------------- kernel 1: build template t (repeat_interleave x2) -----------
__global__ void build_t_kernel(const float* __restrict__ token_init) {
    int s = blockIdx.x;            // 0..575
    int b = blockIdx.y;
    int hh = s / T_, ww = s % T_;
    int d = threadIdx.x;           // 256
    g_t[(b * S_ + s) * DIM + d] =
        token_init[((b * S0 + (hh >> 1)) * S0 + (ww >> 1)) * DIM + d];
}

// ---------------- tiled fp32 GEMM, 32x32 tile, 4 outputs/thread ---------------
// C[M,N] = act( alpha * A@B(^T) + bias ) + resid
// All M,N,K used here are multiples of 32 (no bounds checks).
template<bool TRANSB, bool ACT_GELU, bool RESID, bool BIAS>
__global__ __launch_bounds__(256)
void gemm_tiled(const float* __restrict__ A, const float* __restrict__ Bm,
                const float* __restrict__ bias, const float* __restrict__ R,
                float* __restrict__ C,
                int M, int N, int K, float alpha,
                int sA, int sB, int sC, int sR)
{
    int b = blockIdx.z;
    A += (long)b * sA; Bm += (long)b * sB; C += (long)b * sC;
    if (RESID) R += (long)b * sR;

    __shared__ float As[32][33];
    __shared__ float Bs[32][33];

    const int tid = threadIdx.x;
    const int c   = tid & 31;    // column within tile
    const int rg  = tid >> 5;    // row group 0..7 (4 rows each)
    const int row0 = blockIdx.y * 32;
    const int col0 = blockIdx.x * 32;

    float acc[4] = {0.f, 0.f, 0.f, 0.f};

    for (int k0 = 0; k0 < K; k0 += 32) {
#pragma unroll
        for (int i = 0; i < 4; i++) {
            int idx = tid + i * 256;
            int r = idx >> 5, kk = idx & 31;
            As[r][kk] = A[(long)(row0 + r) * K + k0 + kk];
        }
#pragma unroll
        for (int i = 0; i < 4; i++) {
            int idx = tid + i * 256;
            if (TRANSB) {
                int n = idx >> 5, kk = idx & 31;
                Bs[kk][n] = Bm[(long)(col0 + n) * K + k0 + kk];
            } else {
                int kk = idx >> 5, n = idx & 31;
                Bs[kk][n] = Bm[(long)(k0 + kk) * N + col0 + n];
            }
        }
        __syncthreads();
#pragma unroll
        for (int kk = 0; kk < 32; kk++) {
            float bv = Bs[kk][c];
#pragma unroll
            for (int i = 0; i < 4; i++)
                acc[i] += As[rg * 4 + i][kk] * bv;
        }
        __syncthreads();
    }

#pragma unroll
    for (int i = 0; i < 4; i++) {
        int row = row0 + rg * 4 + i;
        int col = col0 + c;
        float v = acc[i] * alpha;
        if (BIAS)     v += bias[col];
        if (ACT_GELU) v  = gelu_exact(v);
        if (RESID)    v += R[(long)row * N + col];
        C[(long)row * N + col] = v;
    }
}

// ---------------- node_w / node_h: contract over 24 along w (or h) ------------
// mode 0: out s=h    : sum_w adj[b,h,w,p] * t[b,h,w,d]
// mode 1: out s=24+w : sum_h adj[b,h,w,p] * t[b,h,w,d]
__global__ __launch_bounds__(256)
void node_wh_kernel(float rs) {
    __shared__ float adj_s[T_][NP];     // 12 KB
    __shared__ float t_s  [T_][DIM];    // 24 KB
    const int fix  = blockIdx.x;   // h (mode 0) or w (mode 1)
    const int b    = blockIdx.y;
    const int mode = blockIdx.z;
    const int tid  = threadIdx.x;  // 256

    for (int idx = tid; idx < T_ * NP; idx += 256) {
        int m = idx >> 7, p = idx & 127;
        int h = mode ? m : fix;
        int w = mode ? fix : m;
        adj_s[m][p] = g_adj[((b * S_) + h * T_ + w) * NP + p];
    }
    for (int idx = tid; idx < T_ * DIM; idx += 256) {
        int m = idx >> 8, d = idx & 255;
        int h = mode ? m : fix;
        int w = mode ? fix : m;
        t_s[m][d] = g_t[((b * S_) + h * T_ + w) * DIM + d];
    }
    __syncthreads();

    const int d = tid;
    const int srow = mode ? (T_ + fix) : fix;
    for (int pb = 0; pb < NP; pb += 16) {
        float acc[16];
#pragma unroll
        for (int i = 0; i < 16; i++) acc[i] = 0.f;
        for (int m = 0; m < T_; m++) {
            float tv = t_s[m][d];
#pragma unroll
            for (int i = 0; i < 16; i++)
                acc[i] += adj_s[m][pb + i] * tv;
        }
#pragma unroll
        for (int i = 0; i < 16; i++)
            g_tokn[((long)(b * S2 + srow) * NP + pb + i) * DIM + d] = acc[i] * rs;
    }
}

// ---------------- token_fused MLP over the 48-axis ----------------------------
// one thread per (b,p,d); x[s] = token_n[b,s,p,d]
__global__ __launch_bounds__(256)
void token_fused_kernel(const float* __restrict__ w1, const float* __restrict__ b1,
                        const float* __restrict__ w2, const float* __restrict__ b2) {
    __shared__ float w1s[S2][S2 + 1];
    __shared__ float b1s[S2];
    __shared__ float w2s[S2];
    const int tid = threadIdx.x;
    for (int idx = tid; idx < S2 * S2; idx += 256)
        w1s[idx / S2][idx % S2] = w1[idx];
    if (tid < S2) { b1s[tid] = b1[tid]; w2s[tid] = w2[tid]; }
    __syncthreads();

    const int bp = blockIdx.x;        // 0..511 = b*128+p
    const int b  = bp >> 7;
    const int p  = bp & 127;
    const int d  = tid;

    float x[S2];
#pragma unroll
    for (int s = 0; s < S2; s++)
        x[s] = g_tokn[((long)(b * S2 + s) * NP + p) * DIM + d];

    float out = b2[0];
    for (int j = 0; j < S2; j++) {
        float a = b1s[j];
#pragma unroll
        for (int s = 0; s < S2; s++)
            a += x[s] * w1s[s][j];
        out += gelu_exact(a) * w2s[j];
    }
    g_fus[bp * DIM + d] = out;
}

// ---------------- row softmax, N = 128, one block per row ---------------------
__global__ __launch_bounds__(128)
void softmax128_kernel(float* __restrict__ X) {
    const int row = blockIdx.x;
    const int t = threadIdx.x;
    float v = X[row * NP + t];
    __shared__ float red[4];
    float m = v;
#pragma unroll
    for (int o = 16; o; o >>= 1) m = fmaxf(m, __shfl_xor_sync(0xffffffffu, m, o));
    if ((t & 31) == 0) red[t >> 5] = m;
    __syncthreads();
    m = fmaxf(fmaxf(red[0], red[1]), fmaxf(red[2], red[3]));
    float e = expf(v - m);
    __syncthreads();
    float s = e;
#pragma unroll
    for (int o = 16; o; o >>= 1) s += __shfl_xor_sync(0xffffffffu, s, o);
    if ((t & 31) == 0) red[t >> 5] = s;
    __syncthreads();
    s = red[0] + red[1] + red[2] + red[3];
    X[row * NP + t] = e / s;
}

// ---------------- final scatter-broadcast of the 576 unique rows --------------
__global__ __launch_bounds__(64)
void scatter_kernel(float4* __restrict__ out) {
    const int w = blockIdx.x, h = blockIdx.y, b = blockIdx.z;
    const int uh = h / 5;                // (h*24)/120
    const int uw = (w * 24) / 160;
    const float4* src = reinterpret_cast<const float4*>(g_U)
                        + (long)((b * S_) + uh * T_ + uw) * (DIM / 4);
    float4* dst = out + (long)(((b * H_) + h) * W_ + w) * (DIM / 4);
    dst[threadIdx.x] = src[threadIdx.x];
}

// ==============================================================================
extern "C" void kernel_launch(void* const* d_in, const int* in_sizes, int n_in,
                              void* d_out, int out_size) {
    const float* token_init  = (const float*)d_in[0];
    const float* point_token = (const float*)d_in[1];
    const float* nr_w1 = (const float*)d_in[2];
    const float* nr_b1 = (const float*)d_in[3];
    const float* nr_w2 = (const float*)d_in[4];
    const float* nr_b2 = (const float*)d_in[5];
    const float* na_w1 = (const float*)d_in[6];
    const float* na_b1 = (const float*)d_in[7];
    const float* na_w2 = (const float*)d_in[8];
    const float* na_b2 = (const float*)d_in[9];
    const float* tf_w1 = (const float*)d_in[10];
    const float* tf_b1 = (const float*)d_in[11];
    const float* tf_w2 = (const float*)d_in[12];
    const float* tf_b2 = (const float*)d_in[13];
    float* out = (float*)d_out;

    float *t_p, *A0_p, *H_p, *adj_p, *attn_p, *fus_p, *U_p;
    cudaGetSymbolAddress((void**)&t_p,    g_t);
    cudaGetSymbolAddress((void**)&A0_p,   g_A0);
    cudaGetSymbolAddress((void**)&H_p,    g_H);
    cudaGetSymbolAddress((void**)&adj_p,  g_adj);
    cudaGetSymbolAddress((void**)&attn_p, g_attn);
    cudaGetSymbolAddress((void**)&fus_p,  g_fus);
    cudaGetSymbolAddress((void**)&U_p,    g_U);

    const float scale = 0.0625f;                 // dim^-0.5 = 1/16
    const float rs = 0.20412414523193154f;       // 24^-0.5

    // 1. template tokens
    build_t_kernel<<<dim3(S_, B_), 256>>>(token_init);

    // 2. A0 = t @ P^T * scale   [4,576,128]  (shared by both MLP branches)
    gemm_tiled<true, false, false, false><<<dim3(NP/32, S_/32, B_), 256>>>(
        t_p, point_token, nullptr, nullptr, A0_p,
        S_, NP, DIM, scale, S_*DIM, NP*DIM, S_*NP, 0);

    // 3. nr MLP: H = gelu(A0@w1+b1); adj = H@w2+b2
    gemm_tiled<false, true, false, true><<<dim3(HID/32, S_/32, B_), 256>>>(
        A0_p, nr_w1, nr_b1, nullptr, H_p,
        S_, HID, NP, 1.f, S_*NP, 0, S_*HID, 0);
    gemm_tiled<false, false, false, true><<<dim3(NP/32, S_/32, B_), 256>>>(
        H_p, nr_w2, nr_b2, nullptr, adj_p,
        S_, NP, HID, 1.f, S_*HID, 0, S_*NP, 0);

    // 4. node_w / node_h  -> token_n [4,48,128,256]
    node_wh_kernel<<<dim3(T_, B_, 2), 256>>>(rs);

    // 5. token_fused MLP over the 48-axis -> [4,128,256]
    token_fused_kernel<<<dim3(B_ * NP), 256>>>(tf_w1, tf_b1, tf_w2, tf_b2);

    // 6. na MLP on A0 -> attn (pre-softmax), then softmax over 128
    gemm_tiled<false, true, false, true><<<dim3(HID/32, S_/32, B_), 256>>>(
        A0_p, na_w1, na_b1, nullptr, H_p,
        S_, HID, NP, 1.f, S_*NP, 0, S_*HID, 0);
    gemm_tiled<false, false, false, true><<<dim3(NP/32, S_/32, B_), 256>>>(
        H_p, na_w2, na_b2, nullptr, attn_p,
        S_, NP, HID, 1.f, S_*HID, 0, S_*NP, 0);
    softmax128_kernel<<<dim3(B_ * S_), 128>>>(attn_p);

    // 7. U = attn @ token_fused + t   [4,576,256]
    gemm_tiled<false, false, true, false><<<dim3(DIM/32, S_/32, B_), 256>>>(
        attn_p, fus_p, nullptr, t_p, U_p,
        S_, DIM, NP, 1.f, S_*NP, NP*DIM, S_*DIM, S_*DIM);

    // 8. broadcast unique rows to the full [4,19200,256] output
    scatter_kernel<<<dim3(W_, H_, B_), 64>>>((float4*)out);
}

// round 2
// speedup vs baseline: 1.4744x; 1.4744x over previous
#include <cuda_runtime.h>
#include <math.h>

// Problem constants (shapes fixed by the dataset)
#define B_    4
#define S0    12
#define T_    24          // template side (2*s0)
#define S_    576         // T_*T_
#define DIM   256
#define NP    128         // nPnt
#define HID   512         // 4*nPnt
#define S2    48          // new2 = 2*new_size
#define H_    120
#define W_    160

// ---------------- scratch (device globals; no allocation allowed) -------------
__device__ float g_t   [B_ * S_ * DIM];        // template tokens [4,576,256]
__device__ float g_A0  [B_ * S_ * NP];         // t @ P^T / 16
__device__ float g_H   [B_ * S_ * 2 * HID];    // hidden, nr cols [0,512), na [512,1024)
__device__ float g_adj [B_ * S_ * NP];         // node_adj after nr MLP
__device__ float g_attn[B_ * S_ * NP];         // na MLP out, softmax in-place
__device__ float g_tokn[(long)B_ * S2 * NP * DIM];  // token_n [4,48,128,256]
__device__ float g_fus [B_ * NP * DIM];        // token_fused [4,128,256]
__device__ float g_U   [B_ * S_ * DIM];        // unique output rows

__device__ __forceinline__ float gelu_exact(float x) {
    return 0.5f * x * (1.0f + erff(x * 0.70710678118654752440f));
}

// ---------------- kernel 1: build template t (repeat_interleave x2) -----------
__global__ void build_t_kernel(const float* __restrict__ token_init) {
    int s = blockIdx.x;            // 0..575
    int b = blockIdx.y;
    int hh = s / T_, ww = s % T_;
    int d = threadIdx.x;           // 256
    g_t[(b * S_ + s) * DIM + d] =
        token_init[((b * S0 + (hh >> 1)) * S0 + (ww >> 1)) * DIM + d];
}

// ===================== register-blocked SGEMM =================================
// 64x64 tile, BK=16, 128 threads, 8x4 micro-tile per thread.
// C = act( alpha * A @ B(^T) + bias ) + R
// DUAL: blockIdx.z = b*2+branch; branch selects B0/B1, bias0/bias1, C0/C1,
//       plus row offset ofsA into A and column offset ofsC into C.
#define BM 64
#define BN 64
#define BK 16

template<bool TRANSB, bool ACT, bool BIAS, bool RESID, bool DUAL>
__global__ __launch_bounds__(128)
void sgemm(const float* __restrict__ A,
           const float* __restrict__ B0, const float* __restrict__ B1,
           const float* __restrict__ bias0, const float* __restrict__ bias1,
           const float* __restrict__ R,
           float* __restrict__ C0, float* __restrict__ C1,
           int K, float alpha,
           long sA, int lda, int ofsA,
           long sB, int ldb,
           long sC, int ldc, int ofsC,
           long sR)
{
    const int z = blockIdx.z;
    const int b  = DUAL ? (z >> 1) : z;
    const int br = DUAL ? (z & 1) : 0;

    const float* Bw  = (DUAL && br) ? B1 : B0;
    const float* bia = (DUAL && br) ? bias1 : bias0;
    float*       C   = (DUAL && br) ? C1 : C0;

    A  += (long)b * sA + (long)br * ofsA;
    Bw += (long)b * sB;
    C  += (long)b * sC + (long)br * ofsC;
    const float* Rp = RESID ? (R + (long)b * sR) : nullptr;

    __shared__ float As[BK][BM + 4];
    __shared__ float Bs[BK][BN + 4];

    const int tid  = threadIdx.x;
    const int row0 = blockIdx.y * BM;
    const int col0 = blockIdx.x * BN;

    // A-load indices (transposed store)
    const int ar = tid >> 2;          // 0..31
    const int ac = (tid & 3) * 4;     // 0,4,8,12
    // B-load indices (no-trans: direct float4 rows)
    const int bkk = tid >> 4;         // 0..7
    const int bn  = (tid & 15) * 4;   // 0..60
    // B-load indices (trans: like A)
    const int brn = tid >> 2;
    const int bc  = (tid & 3) * 4;

    // compute indices
    const int tn = tid & 15;          // 0..15
    const int tm = tid >> 4;          // 0..7
    const int m0 = tm * 8;
    const int n0 = tn * 4;

    float acc[8][4];
#pragma unroll
    for (int i = 0; i < 8; i++)
#pragma unroll
        for (int j = 0; j < 4; j++) acc[i][j] = 0.f;

    float4 aR[2], bR[2];
    const int kTiles = K / BK;

    // prologue: load tile 0 into regs
    {
        const int k0 = 0;
#pragma unroll
        for (int p = 0; p < 2; p++)
            aR[p] = *(const float4*)&A[(long)(row0 + ar + p * 32) * lda + k0 + ac];
        if (TRANSB) {
#pragma unroll
            for (int p = 0; p < 2; p++)
                bR[p] = *(const float4*)&Bw[(long)(col0 + brn + p * 32) * ldb + k0 + bc];
        } else {
#pragma unroll
            for (int p = 0; p < 2; p++)
                bR[p] = *(const float4*)&Bw[(long)(k0 + bkk + p * 8) * ldb + col0 + bn];
        }
    }

    for (int t = 0; t < kTiles; t++) {
        // regs -> smem
#pragma unroll
        for (int p = 0; p < 2; p++) {
            As[ac + 0][ar + p * 32] = aR[p].x;
            As[ac + 1][ar + p * 32] = aR[p].y;
            As[ac + 2][ar + p * 32] = aR[p].z;
            As[ac + 3][ar + p * 32] = aR[p].w;
        }
        if (TRANSB) {
#pragma unroll
            for (int p = 0; p < 2; p++) {
                Bs[bc + 0][brn + p * 32] = bR[p].x;
                Bs[bc + 1][brn + p * 32] = bR[p].y;
                Bs[bc + 2][brn + p * 32] = bR[p].z;
                Bs[bc + 3][brn + p * 32] = bR[p].w;
            }
        } else {
#pragma unroll
            for (int p = 0; p < 2; p++)
                *(float4*)&Bs[bkk + p * 8][bn] = bR[p];
        }
        __syncthreads();

        // prefetch next tile
        if (t + 1 < kTiles) {
            const int k0 = (t + 1) * BK;
#pragma unroll
            for (int p = 0; p < 2; p++)
                aR[p] = *(const float4*)&A[(long)(row0 + ar + p * 32) * lda + k0 + ac];
            if (TRANSB) {
#pragma unroll
                for (int p = 0; p < 2; p++)
                    bR[p] = *(const float4*)&Bw[(long)(col0 + brn + p * 32) * ldb + k0 + bc];
            } else {
#pragma unroll
                for (int p = 0; p < 2; p++)
                    bR[p] = *(const float4*)&Bw[(long)(k0 + bkk + p * 8) * ldb + col0 + bn];
            }
        }

        // compute
#pragma unroll
        for (int kk = 0; kk < BK; kk++) {
            float4 a0 = *(const float4*)&As[kk][m0];
            float4 a1 = *(const float4*)&As[kk][m0 + 4];
            float4 bb = *(const float4*)&Bs[kk][n0];
            float am[8] = {a0.x, a0.y, a0.z, a0.w, a1.x, a1.y, a1.z, a1.w};
#pragma unroll
            for (int i = 0; i < 8; i++) {
                acc[i][0] += am[i] * bb.x;
                acc[i][1] += am[i] * bb.y;
                acc[i][2] += am[i] * bb.z;
                acc[i][3] += am[i] * bb.w;
            }
        }
        __syncthreads();
    }

    // epilogue
    float bf[4] = {0.f, 0.f, 0.f, 0.f};
    if (BIAS) {
#pragma unroll
        for (int j = 0; j < 4; j++) bf[j] = bia[col0 + n0 + j];
    }
#pragma unroll
    for (int i = 0; i < 8; i++) {
        const int row = row0 + m0 + i;
        float4 v;
        v.x = acc[i][0] * alpha + bf[0];
        v.y = acc[i][1] * alpha + bf[1];
        v.z = acc[i][2] * alpha + bf[2];
        v.w = acc[i][3] * alpha + bf[3];
        if (ACT) {
            v.x = gelu_exact(v.x); v.y = gelu_exact(v.y);
            v.z = gelu_exact(v.z); v.w = gelu_exact(v.w);
        }
        if (RESID) {
            float4 r = *(const float4*)&Rp[(long)row * ldc + col0 + n0];
            v.x += r.x; v.y += r.y; v.z += r.z; v.w += r.w;
        }
        *(float4*)&C[(long)row * ldc + col0 + n0] = v;
    }
}

// ---------------- node_w / node_h: contract over 24 along w (or h) ------------
__global__ __launch_bounds__(256)
void node_wh_kernel(float rs) {
    __shared__ float adj_s[T_][NP];     // 12 KB
    __shared__ float t_s  [T_][DIM];    // 24 KB
    const int fix  = blockIdx.x;
    const int b    = blockIdx.y;
    const int mode = blockIdx.z;
    const int tid  = threadIdx.x;

    for (int idx = tid; idx < T_ * NP; idx += 256) {
        int m = idx >> 7, p = idx & 127;
        int h = mode ? m : fix;
        int w = mode ? fix : m;
        adj_s[m][p] = g_adj[((b * S_) + h * T_ + w) * NP + p];
    }
    for (int idx = tid; idx < T_ * DIM; idx += 256) {
        int m = idx >> 8, d = idx & 255;
        int h = mode ? m : fix;
        int w = mode ? fix : m;
        t_s[m][d] = g_t[((b * S_) + h * T_ + w) * DIM + d];
    }
    __syncthreads();

    const int d = tid;
    const int srow = mode ? (T_ + fix) : fix;
#pragma unroll
    for (int pb = 0; pb < 8; pb++) {
        float acc[16];
#pragma unroll
        for (int i = 0; i < 16; i++) acc[i] = 0.f;
        for (int m = 0; m < T_; m++) {
            float tv = t_s[m][d];
            const float4* ap = (const float4*)&adj_s[m][pb * 16];
            float4 a0 = ap[0], a1 = ap[1], a2 = ap[2], a3 = ap[3];
            acc[ 0] += a0.x * tv; acc[ 1] += a0.y * tv; acc[ 2] += a0.z * tv; acc[ 3] += a0.w * tv;
            acc[ 4] += a1.x * tv; acc[ 5] += a1.y * tv; acc[ 6] += a1.z * tv; acc[ 7] += a1.w * tv;
            acc[ 8] += a2.x * tv; acc[ 9] += a2.y * tv; acc[10] += a2.z * tv; acc[11] += a2.w * tv;
            acc[12] += a3.x * tv; acc[13] += a3.y * tv; acc[14] += a3.z * tv; acc[15] += a3.w * tv;
        }
#pragma unroll
        for (int i = 0; i < 16; i++)
            g_tokn[((long)(b * S2 + srow) * NP + pb * 16 + i) * DIM + d] = acc[i] * rs;
    }
}

// ---------------- token_fused MLP over the 48-axis ----------------------------
__global__ __launch_bounds__(256)
void token_fused_kernel(const float* __restrict__ w1, const float* __restrict__ b1,
                        const float* __restrict__ w2, const float* __restrict__ b2) {
    __shared__ float w1t[S2][S2];   // transposed: w1t[j][s] = w1[s][j]
    __shared__ float b1s[S2];
    __shared__ float w2s[S2];
    const int tid = threadIdx.x;
    for (int idx = tid; idx < S2 * S2; idx += 256) {
        int s = idx / S2, j = idx % S2;
        w1t[j][s] = w1[idx];
    }
    if (tid < S2) { b1s[tid] = b1[tid]; w2s[tid] = w2[tid]; }
    __syncthreads();

    const int bp = blockIdx.x;        // 0..511 = b*128+p
    const int b  = bp >> 7;
    const int p  = bp & 127;
    const int d  = tid;

    float x[S2];
#pragma unroll
    for (int s = 0; s < S2; s++)
        x[s] = g_tokn[((long)(b * S2 + s) * NP + p) * DIM + d];

    float out = b2[0];
    for (int j = 0; j < S2; j++) {
        float a = b1s[j];
        const float4* wr = (const float4*)&w1t[j][0];
#pragma unroll
        for (int s4 = 0; s4 < S2 / 4; s4++) {
            float4 wv = wr[s4];
            a += x[s4 * 4 + 0] * wv.x + x[s4 * 4 + 1] * wv.y
               + x[s4 * 4 + 2] * wv.z + x[s4 * 4 + 3] * wv.w;
        }
        out += gelu_exact(a) * w2s[j];
    }
    g_fus[bp * DIM + d] = out;
}

// ---------------- row softmax, N = 128, one block per row ---------------------
__global__ __launch_bounds__(128)
void softmax128_kernel(float* __restrict__ X) {
    const int row = blockIdx.x;
    const int t = threadIdx.x;
    float v = X[row * NP + t];
    __shared__ float red[4];
    float m = v;
#pragma unroll
    for (int o = 16; o; o >>= 1) m = fmaxf(m, __shfl_xor_sync(0xffffffffu, m, o));
    if ((t & 31) == 0) red[t >> 5] = m;
    __syncthreads();
    m = fmaxf(fmaxf(red[0], red[1]), fmaxf(red[2], red[3]));
    float e = expf(v - m);
    __syncthreads();
    float s = e;
#pragma unroll
    for (int o = 16; o; o >>= 1) s += __shfl_xor_sync(0xffffffffu, s, o);
    if ((t & 31) == 0) red[t >> 5] = s;
    __syncthreads();
    s = red[0] + red[1] + red[2] + red[3];
    X[row * NP + t] = e / s;
}

// ---------------- final scatter-broadcast of the 576 unique rows --------------
__global__ __launch_bounds__(256)
void scatter_kernel(float4* __restrict__ out) {
    const int wq = threadIdx.x >> 6;          // 0..3
    const int dq = threadIdx.x & 63;          // 0..63
    const int w  = blockIdx.x * 4 + wq;
    const int h  = blockIdx.y;
    const int b  = blockIdx.z;
    const int uh = h / 5;
    const int uw = (w * 24) / 160;
    const float4* src = reinterpret_cast<const float4*>(g_U)
                        + (long)((b * S_) + uh * T_ + uw) * (DIM / 4);
    float4* dst = out + (long)(((b * H_) + h) * W_ + w) * (DIM / 4);
    dst[dq] = src[dq];
}

// ==============================================================================
extern "C" void kernel_launch(void* const* d_in, const int* in_sizes, int n_in,
                              void* d_out, int out_size) {
    const float* token_init  = (const float*)d_in[0];
    const float* point_token = (const float*)d_in[1];
    const float* nr_w1 = (const float*)d_in[2];
    const float* nr_b1 = (const float*)d_in[3];
    const float* nr_w2 = (const float*)d_in[4];
    const float* nr_b2 = (const float*)d_in[5];
    const float* na_w1 = (const float*)d_in[6];
    const float* na_b1 = (const float*)d_in[7];
    const float* na_w2 = (const float*)d_in[8];
    const float* na_b2 = (const float*)d_in[9];
    const float* tf_w1 = (const float*)d_in[10];
    const float* tf_b1 = (const float*)d_in[11];
    const float* tf_w2 = (const float*)d_in[12];
    const float* tf_b2 = (const float*)d_in[13];
    float* out = (float*)d_out;

    float *t_p, *A0_p, *H_p, *adj_p, *attn_p, *fus_p, *U_p;
    cudaGetSymbolAddress((void**)&t_p,    g_t);
    cudaGetSymbolAddress((void**)&A0_p,   g_A0);
    cudaGetSymbolAddress((void**)&H_p,    g_H);
    cudaGetSymbolAddress((void**)&adj_p,  g_adj);
    cudaGetSymbolAddress((void**)&attn_p, g_attn);
    cudaGetSymbolAddress((void**)&fus_p,  g_fus);
    cudaGetSymbolAddress((void**)&U_p,    g_U);

    const float scale = 0.0625f;               // dim^-0.5
    const float rs = 0.20412414523193154f;     // 24^-0.5

    // 1. template tokens
    build_t_kernel<<<dim3(S_, B_), 256>>>(token_init);

    // 2. A0 = t @ P^T * scale  [4,576,128]
    sgemm<true, false, false, false, false><<<dim3(NP/BN, S_/BM, B_), 128>>>(
        t_p, point_token, nullptr, nullptr, nullptr, nullptr, A0_p, nullptr,
        DIM, scale,
        (long)S_*DIM, DIM, 0,
        (long)NP*DIM, DIM,
        (long)S_*NP, NP, 0, 0);

    // 3. fc1 (nr & na merged): H = gelu(A0 @ w1 + b1)   [4,576,1024]
    sgemm<false, true, true, false, true><<<dim3(HID/BN, S_/BM, 2*B_), 128>>>(
        A0_p, nr_w1, na_w1, nr_b1, na_b1, nullptr, H_p, H_p,
        NP, 1.f,
        (long)S_*NP, NP, 0,
        0, HID,
        (long)S_*2*HID, 2*HID, HID, 0);

    // 4. fc2 (nr & na merged): adj / attn = H @ w2 + b2
    sgemm<false, false, true, false, true><<<dim3(NP/BN, S_/BM, 2*B_), 128>>>(
        H_p, nr_w2, na_w2, nr_b2, na_b2, nullptr, adj_p, attn_p,
        HID, 1.f,
        (long)S_*2*HID, 2*HID, HID,
        0, NP,
        (long)S_*NP, NP, 0, 0);

    // 5. node_w / node_h -> token_n
    node_wh_kernel<<<dim3(T_, B_, 2), 256>>>(rs);

    // 6. token_fused MLP over the 48-axis -> [4,128,256]
    token_fused_kernel<<<dim3(B_ * NP), 256>>>(tf_w1, tf_b1, tf_w2, tf_b2);

    // 7. softmax over the 128 points
    softmax128_kernel<<<dim3(B_ * S_), 128>>>(attn_p);

    // 8. U = attn @ token_fused + t   [4,576,256]
    sgemm<false, false, false, true, false><<<dim3(DIM/BN, S_/BM, B_), 128>>>(
        attn_p, fus_p, nullptr, nullptr, nullptr, t_p, U_p, nullptr,
        NP, 1.f,
        (long)S_*NP, NP, 0,
        (long)NP*DIM, DIM,
        (long)S_*DIM, DIM, 0, (long)S_*DIM);

    // 9. broadcast unique rows to the full [4,19200,256] output
    scatter_kernel<<<dim3(W_/4, H_, B_), 256>>>((float4*)out);
}